// round 17
// baseline (speedup 1.0000x reference)
#include <cuda_runtime.h>
#include <cuda_fp16.h>
#include <math.h>
#include <stdint.h>

#define BATCH   128
#define TT      504
#define TF      502
#define TC      500
#define NSTEP   2000
#define NT      512

// ---------------- transposed-weight offsets (elements) ----------------
#define OFF_FWC    0          // (192,328)
#define OFF_FWCG   62976      // (192,192)
#define OFF_G1IH   99840      // (480,272)
#define OFF_G1HH   230400     // (480,160)
#define OFF_GLU1   307200     // (160,160)
#define OFF_G2IH   332800     // (384,240)
#define OFF_G2HH   424960     // (384,128)
#define OFF_GLU2   474112     // (128,128)
#define OFF_G3IH   490496     // (384,208)
#define OFF_G3HH   570368     // (384,128)
#define OFF_GLU3   619520     // (128,128)
#define OFF_SKIP   635904     // (128,688)
#define OFF_SKIPG  723968     // (128,128)
#define OFF_SIG    740352     // (40,128)
#define OFF_GOUT   745472     // (4,192)
#define WT_TOTAL   746240

// ---------------- streaming schedule ----------------
#define NSCHED  37
#define TOTAL_CHUNKS (NSTEP * NSCHED)
#define NB      3
#define BUFB    49152

__constant__ int c_off[NSCHED] = {
    0, 24576, 49152,                                   // FWC (CK=128)
    62976, 87552,                                      // FWCG (CK=128)
    99840, 124320, 148800, 173280, 197760, 222240,     // G1IH (CK=51)
    230400, 254880, 279360, 303840,                    // G1HH (CK=51)
    307200, 327680,                                    // GLU1 (CK=128)
    332800, 357376, 381952, 406528,                    // G2IH (CK=64)
    424960, 449536,                                    // G2HH (CK=64)
    474112,                                            // GLU2
    490496, 515072, 539648, 564224,                    // G3IH (CK=64)
    570368, 594944,                                    // G3HH (CK=64)
    619520,                                            // GLU3
    635904, 660480, 685056, 709632,                    // SKIP (CK=192)
    723968,                                            // SKIPG
    740352                                             // SIG
};
__constant__ int c_bytes[NSCHED] = {
    49152, 49152, 27648,
    49152, 24576,
    48960, 48960, 48960, 48960, 48960, 16320,
    48960, 48960, 48960, 6720,
    40960, 10240,
    49152, 49152, 49152, 36864,
    49152, 49152,
    32768,
    49152, 49152, 49152, 12288,
    49152, 49152,
    32768,
    49152, 49152, 49152, 28672,
    32768,
    10240
};

// ---------------- device scratch ----------------
__device__ float  g_x[BATCH * TF * 64];
__device__ float  g_y[BATCH * TC * 128];
__device__ float  g_cond[BATCH * TC * 320];
__device__ float  g_gain[NSTEP * BATCH];
__device__ float  g_wt[WT_TOTAL];              // fp32 (gout path)
__device__ __align__(16) __half g_wth[WT_TOTAL]; // fp16 transposed [in][out]

__device__ __forceinline__ float sigf(float x) { return 1.0f / (1.0f + expf(-x)); }

// ---------------- mbarrier / cluster helpers ----------------
__device__ __forceinline__ uint32_t su32(const void* p) {
    return (uint32_t)__cvta_generic_to_shared(p);
}
#define MBAR_INIT(a, n) \
    asm volatile("mbarrier.init.shared.b64 [%0], %1;" :: "r"(a), "r"((uint32_t)(n)) : "memory")
#define MBAR_EXPECT_TX(a, b) \
    asm volatile("mbarrier.arrive.expect_tx.shared.b64 _, [%0], %1;" :: "r"(a), "r"((uint32_t)(b)) : "memory")
#define MBAR_ARRIVE_CLUSTER0(a) \
    asm volatile("{\n\t.reg .b32 ra;\n\tmapa.shared::cluster.u32 ra, %0, 0;\n\t" \
                 "mbarrier.arrive.shared::cluster.b64 _, [ra];\n\t}" :: "r"(a) : "memory")
#define MBAR_WAIT(a, par) do { \
    uint32_t _m = (a); uint32_t _p = (par); uint32_t _d; \
    asm volatile("{\n\t.reg .pred p;\n\t" \
        "mbarrier.try_wait.parity.acquire.cta.shared::cta.b64 p, [%1], %2;\n\t" \
        "selp.b32 %0, 1, 0, p;\n\t}" : "=r"(_d) : "r"(_m), "r"(_p) : "memory"); \
    if (!_d) { \
        asm volatile("{\n\t.reg .pred P1;\n\tWL_%=:\n\t" \
            "mbarrier.try_wait.parity.acquire.cta.shared::cta.b64 P1, [%0], %1, 0x989680;\n\t" \
            "@P1 bra.uni WD_%=;\n\tbra.uni WL_%=;\n\tWD_%=:\n\t}" \
            :: "r"(_m), "r"(_p) : "memory"); \
    } \
} while (0)
#define CLUSTER_SYNC() do { \
    asm volatile("barrier.cluster.arrive.aligned;" ::: "memory"); \
    asm volatile("barrier.cluster.wait.aligned;" ::: "memory"); \
} while (0)

__device__ __forceinline__ void mc_issue(uint32_t dst, const void* src, int bytes, uint32_t mbar) {
    asm volatile(
        "cp.async.bulk.shared::cluster.global.mbarrier::complete_tx::bytes.multicast::cluster "
        "[%0], [%1], %2, [%3], %4;"
        :: "r"(dst), "l"(src), "r"(bytes), "r"(mbar), "h"((uint16_t)3)
        : "memory");
}

// ---------------- stream context ----------------
struct SC {
    int cg;              // global chunk counter
    uint32_t fb, eb;     // smem addrs of full[0] / empty[0] (8B stride)
    uint32_t bufa;       // smem addr of buffer 0
    const char* bufp;    // generic ptr to buffer 0
    int rank;
};

__device__ __forceinline__ void chunk_wait(SC& st) {
    int slot = st.cg % NB;
    int par = (st.cg / NB) & 1;
    MBAR_WAIT(st.fb + slot * 8, par);
}
__device__ __forceinline__ void chunk_release(SC& st) {
    __syncthreads();
    if (threadIdx.x == 0) {
        int slot = st.cg % NB;
        int nxt = st.cg + NB;
        if (nxt < TOTAL_CHUNKS) {
            int m = nxt % NSCHED;
            MBAR_EXPECT_TX(st.fb + slot * 8, c_bytes[m]);
        }
        MBAR_ARRIVE_CLUSTER0(st.eb + slot * 8);
        if (st.rank == 0 && nxt < TOTAL_CHUNKS) {
            MBAR_WAIT(st.eb + slot * 8, (st.cg / NB) & 1);
            int m = nxt % NSCHED;
            mc_issue(st.bufa + slot * BUFB,
                     (const char*)g_wth + (size_t)c_off[m] * 2,
                     c_bytes[m], st.fb + slot * 8);
        }
    }
    st.cg++;
}

// ---------------- fused weight transpose ----------------
struct WP { const float* p[15]; };
__constant__ int T_OFF[15] = {OFF_FWC, OFF_FWCG, OFF_G1IH, OFF_G1HH, OFF_GLU1,
                              OFF_G2IH, OFF_G2HH, OFF_GLU2, OFF_G3IH, OFF_G3HH,
                              OFF_GLU3, OFF_SKIP, OFF_SKIPG, OFF_SIG, OFF_GOUT};
__constant__ int T_OUT[15] = {192, 192, 480, 480, 160, 384, 384, 128, 384, 384, 128, 128, 128, 40, 4};
__constant__ int T_IN [15] = {328, 192, 272, 160, 160, 240, 128, 128, 208, 128, 128, 688, 128, 128, 192};

__global__ void k_transpose_all(WP wp) {
    int l = blockIdx.y;
    int i = blockIdx.x * blockDim.x + threadIdx.x;
    int out = T_OUT[l], in = T_IN[l];
    if (i < out * in) {
        int o = i / in, k = i - o * in;
        float w = wp.p[l][i];
        g_wt[T_OFF[l] + k * out + o] = w;
        g_wth[T_OFF[l] + k * out + o] = __float2half(w);
    }
}

// ---------------- fd1 ----------------
__global__ void k_fd1n(const float* __restrict__ feat, const int* __restrict__ period,
                       const float* __restrict__ pembed, const float* __restrict__ fd1) {
    int b = blockIdx.x;
    __shared__ float wd1[64 * 33];
    int tid = threadIdx.x;
    for (int i = tid; i < 64 * 32; i += 256) {
        int o = i >> 5, k = i & 31;
        wd1[o * 33 + k] = fd1[i];
    }
    __syncthreads();
    int warp = tid >> 5, lane = tid & 31;
    for (int t = warp; t < TF; t += 8) {
        int per = period[b * TT + t + 2];
        per = min(max(per, 32), 254);
        float v;
        if (lane < 20) v = feat[(b * TT + t + 2) * 20 + lane];
        else           v = pembed[(per - 32) * 12 + (lane - 20)];
        float a0 = 0.0f, a1 = 0.0f;
#pragma unroll
        for (int k = 0; k < 32; k++) {
            float xk = __shfl_sync(0xffffffffu, v, k);
            a0 = fmaf(wd1[lane * 33 + k], xk, a0);
            a1 = fmaf(wd1[(lane + 32) * 33 + k], xk, a1);
        }
        g_x[(b * TF + t) * 64 + lane] = tanhf(a0);
        g_x[(b * TF + t) * 64 + lane + 32] = tanhf(a1);
    }
}

// ---------------- conv1d ----------------
#define CONV_SMEM ((128 * 193 + 192) * 4)
__global__ void k_convn(const float* __restrict__ wconv) {
    int b = blockIdx.x;
    int t0 = blockIdx.y * 250;
    extern __shared__ float smc[];
    float* wc = smc;
    float* xin = smc + 128 * 193;
    int tid = threadIdx.x;
    for (int i = tid; i < 128 * 192; i += 128) {
        int oc = i / 192, k = i - oc * 192;
        wc[oc * 193 + k] = wconv[i];
    }
    __syncthreads();
    for (int t = t0; t < t0 + 250; t++) {
        for (int i = tid; i < 192; i += 128)
            xin[i] = g_x[(b * TF + t + (i >> 6)) * 64 + (i & 63)];
        __syncthreads();
        float acc = 0.0f;
        const float* w = wc + tid * 193;
#pragma unroll 8
        for (int ic = 0; ic < 64; ic++) {
            acc = fmaf(w[ic * 3 + 0], xin[ic], acc);
            acc = fmaf(w[ic * 3 + 1], xin[64 + ic], acc);
            acc = fmaf(w[ic * 3 + 2], xin[128 + ic], acc);
        }
        g_y[(b * TC + t) * 128 + tid] = tanhf(acc);
        __syncthreads();
    }
}

// ---------------- fd2 + gains ----------------
#define FD2_SMEM ((320 * 129 + 128 + 320 + 80) * 4)
__global__ void k_fd2n(const float* __restrict__ fd2, const float* __restrict__ cg_w,
                       const float* __restrict__ cg_b) {
    int b = blockIdx.x;
    extern __shared__ float smf[];
    float* wf = smf;
    float* ybuf = wf + 320 * 129;
    float* condb = ybuf + 128;
    float* cgw = condb + 320;
    int tid = threadIdx.x;
    for (int i = tid; i < 320 * 128; i += 320) {
        int o = i >> 7, k = i & 127;
        wf[o * 129 + k] = fd2[i];
    }
    if (tid < 80) cgw[tid] = cg_w[tid];
    __syncthreads();
    float cb = cg_b[0];
    for (int t = 0; t < TC; t++) {
        if (tid < 128) ybuf[tid] = g_y[(b * TC + t) * 128 + tid];
        __syncthreads();
        float acc = 0.0f;
        const float* w = wf + tid * 129;
#pragma unroll 8
        for (int k = 0; k < 128; k++) acc = fmaf(w[k], ybuf[k], acc);
        float cv = tanhf(acc);
        condb[tid] = cv;
        g_cond[((size_t)(b * TC + t)) * 320 + tid] = cv;
        __syncthreads();
        if (tid < 4) {
            float a = cb;
            const float* cc = condb + tid * 80;
#pragma unroll 8
            for (int k = 0; k < 80; k++) a = fmaf(cgw[k], cc[k], a);
            float g = 0.2f + 0.8f * sigf(a);
            g = fminf(fmaxf(g, 0.001f), 20.0f);
            g_gain[(t * 4 + tid) * BATCH + b] = g;
        }
    }
}

// ================= scan: BPC=1, fp16 weights multicast-streamed =================
// streamed matvec: weights arrive in smem chunks (CK rows each).
template <int IN, int OUT, int CK, int ACT>
__device__ __forceinline__ void matvec_s(SC& st, const float* __restrict__ x,
                                         float* __restrict__ y, float* __restrict__ red) {
    constexpr int RG = OUT / 8;
    constexpr int S0 = NT / RG;
    constexpr int S = (S0 > 32) ? 32 : S0;
    constexpr int NCH = (IN + CK - 1) / CK;
    static_assert(S * OUT <= 4096, "red overflow");
    static_assert(CK * OUT * 2 <= BUFB, "chunk too big");
    int tid = threadIdx.x;
    int sl = tid / RG;
    int rg = tid - sl * RG;
    float a[8];
#pragma unroll
    for (int i = 0; i < 8; i++) a[i] = 0.0f;
#pragma unroll
    for (int c = 0; c < NCH; c++) {
        chunk_wait(st);
        if (sl < S) {
            int slot = st.cg % NB;
            const uint4* __restrict__ W4 =
                reinterpret_cast<const uint4*>(st.bufp + slot * BUFB) + rg;
            int k0 = c * CK;
            int k1 = (k0 + CK < IN) ? (k0 + CK) : IN;
#pragma unroll 4
            for (int k = k0 + sl; k < k1; k += S) {
                uint4 wv = W4[(k - k0) * RG];
                float xk = x[k];
                const __half2* hp = reinterpret_cast<const __half2*>(&wv);
#pragma unroll
                for (int i = 0; i < 4; i++) {
                    float2 w = __half22float2(hp[i]);
                    a[2 * i]     = fmaf(w.x, xk, a[2 * i]);
                    a[2 * i + 1] = fmaf(w.y, xk, a[2 * i + 1]);
                }
            }
        }
        chunk_release(st);   // includes __syncthreads
    }
    if (sl < S) {
        float4* r = reinterpret_cast<float4*>(red + sl * OUT + rg * 8);
        r[0] = make_float4(a[0], a[1], a[2], a[3]);
        r[1] = make_float4(a[4], a[5], a[6], a[7]);
    }
    __syncthreads();
    for (int o = tid; o < OUT; o += NT) {
        float t = 0.0f;
#pragma unroll
        for (int ss = 0; ss < S; ss++) t += red[ss * OUT + o];
        if (ACT == 1) t = tanhf(t);
        y[o] = t;
    }
    __syncthreads();
}

// fp32 matvec (gout only; OUT=4, direct LDG)
template <int IN, int OUT, int ACT>
__device__ __forceinline__ void matvec_f(const float* __restrict__ Wt,
                                         const float* __restrict__ x,
                                         float* __restrict__ y,
                                         float* __restrict__ red) {
    constexpr int RG = OUT / 4;
    constexpr int S0 = NT / RG;
    constexpr int S = (S0 > 32) ? 32 : S0;
    int tid = threadIdx.x;
    int sl = tid / RG;
    int rg = tid - sl * RG;
    if (sl < S) {
        float4 a = make_float4(0.f, 0.f, 0.f, 0.f);
        const float4* __restrict__ W4 = reinterpret_cast<const float4*>(Wt) + rg;
#pragma unroll 16
        for (int k = sl; k < IN; k += S) {
            float xk = x[k];
            float4 w = __ldg(&W4[k * RG]);
            a.x = fmaf(w.x, xk, a.x); a.y = fmaf(w.y, xk, a.y);
            a.z = fmaf(w.z, xk, a.z); a.w = fmaf(w.w, xk, a.w);
        }
        *(reinterpret_cast<float4*>(red + sl * OUT) + rg) = a;
    }
    __syncthreads();
    for (int o = tid; o < OUT; o += NT) {
        float t = 0.0f;
#pragma unroll
        for (int ss = 0; ss < S; ss++) t += red[ss * OUT + o];
        if (ACT == 1) t = tanhf(t);
        y[o] = t;
    }
    __syncthreads();
}

template <int H, int IN, int CKI, int CKH>
__device__ __forceinline__ void gru_glu(SC& st, const float* x, float* h, float* g,
                                        float* gi, float* gh, float* red) {
    matvec_s<IN, 3 * H, CKI, 0>(st, x, gi, red);
    matvec_s<H, 3 * H, CKH, 0>(st, h, gh, red);
    int tid = threadIdx.x;
    if (tid < H) {
        int o = tid;
        float r = sigf(gi[o] + gh[o]);
        float z = sigf(gi[H + o] + gh[H + o]);
        float n = tanhf(gi[2 * H + o] + r * gh[2 * H + o]);
        h[o] = (1.0f - z) * n + z * h[o];
    }
    __syncthreads();
    matvec_s<H, H, 128, 0>(st, h, gh, red);
    if (tid < H) g[tid] = h[tid] * sigf(gh[tid]);
    __syncthreads();
}

#define SCAN_DSMEM (NB * BUFB + 4096 * 4)

__global__ __launch_bounds__(NT) __cluster_dims__(2, 1, 1)
void k_scan(const int* __restrict__ period,
            const float* __restrict__ gout_b,
            float* __restrict__ out) {
    int b0 = blockIdx.x;                           // one batch elem per CTA
    uint32_t rank;
    asm("mov.u32 %0, %%cluster_ctarank;" : "=r"(rank));

    extern __shared__ char dsm[];
    char*  bufs = dsm;                             // NB x BUFB
    float* red  = (float*)(dsm + NB * BUFB);       // 4096 floats
    __shared__ __align__(8) unsigned long long s_bar[6];  // full[3], empty[3]
    __shared__ __align__(16) float exc[256];
    __shared__ __align__(16) float xcat[328];
    __shared__ __align__(16) float s1[160], s2[128], s3[128];
    __shared__ __align__(16) float buf_t[192];
    __shared__ __align__(16) float fwc_out[192];
    __shared__ __align__(16) float gi[480], gh[480];
    __shared__ __align__(16) float g1b[160], g2b[128], g3b[128];
    __shared__ __align__(16) float skin[688];
    __shared__ __align__(16) float skipv[128];
    __shared__ __align__(16) float pgb[4];
    __shared__ float sgain[1];
    __shared__ int   sper[1];
    int tid = threadIdx.x;

    SC st;
    st.cg = 0;
    st.fb = su32(&s_bar[0]);
    st.eb = su32(&s_bar[3]);
    st.bufa = su32(bufs);
    st.bufp = bufs;
    st.rank = (int)rank;

    // init barriers + state
    if (tid == 0) {
        for (int i = 0; i < NB; i++) {
            MBAR_INIT(st.fb + i * 8, 1);
            MBAR_INIT(st.eb + i * 8, 2);
        }
    }
    for (int i = tid; i < 256; i += NT) exc[i] = 0.0f;
    for (int i = tid; i < 328; i += NT) xcat[i] = 0.0f;
    for (int i = tid; i < 160; i += NT) s1[i] = 0.0f;
    for (int i = tid; i < 128; i += NT) { s2[i] = 0.0f; s3[i] = 0.0f; }
    __syncthreads();
    if (tid == 0) {
        for (int i = 0; i < NB; i++) MBAR_EXPECT_TX(st.fb + i * 8, c_bytes[i]);
    }
    __syncthreads();
    CLUSTER_SYNC();   // all barriers init'd + expects set before any multicast
    if (rank == 0 && tid == 0) {
        for (int i = 0; i < NB; i++)
            mc_issue(st.bufa + i * BUFB, (const char*)g_wth + (size_t)c_off[i] * 2,
                     c_bytes[i], st.fb + i * 8);
    }

    int base = 0;
    for (int s = 0; s < NSTEP; s++) {
        int frame = s >> 2, sub = s & 3;
        if (tid == 0) {
            int p = period[b0 * TT + 3 + frame];
            sper[0] = min(max(p, 32), 254);
        } else if (tid == 1) {
            sgain[0] = g_gain[s * BATCH + b0];
        }
        if (tid < 164) xcat[tid] = xcat[164 + tid];
        __syncthreads();
        if (tid < 164) {
            int j = tid;
            float invg = 1.0f / (1e-5f + sgain[0]);
            float v;
            if (j < 80) {
                v = g_cond[((size_t)(b0 * TC + frame)) * 320 + sub * 80 + j];
            } else if (j < 124) {
                int i2 = j - 80;
                int idx = 254 - sper[0] + i2;
                if (idx >= 256) idx -= sper[0];
                idx = max(0, min(255, idx));
                v = exc[(base + idx) & 255] * invg;
            } else {
                v = exc[(base + 216 + (j - 124)) & 255] * invg;
            }
            xcat[164 + j] = v;
        }
        __syncthreads();

        matvec_s<328, 192, 128, 1>(st, xcat, buf_t, red);              // FWC
        matvec_s<192, 192, 128, 0>(st, buf_t, gh, red);                // FWCG
        if (tid < 192) fwc_out[tid] = buf_t[tid] * sigf(gh[tid]);
        __syncthreads();

        matvec_f<192, 4, 0>(g_wt + OFF_GOUT, fwc_out, pgb, red);       // gout (fp32 LDG)
        if (tid < 4) pgb[tid] = sigf(pgb[tid] + gout_b[tid]);
        __syncthreads();

        if (tid < 272) {
            int j = tid;
            float v;
            if (j < 192) v = fwc_out[j];
            else if (j < 232) v = pgb[0] * xcat[164 + 82 + (j - 192)];
            else v = xcat[164 + 124 + (j - 232)];
            skin[j] = v;
        }
        __syncthreads();
        gru_glu<160, 272, 51, 51>(st, skin, s1, g1b, gi, gh, red);     // G1IH,G1HH,GLU1

        if (tid < 240) {
            int j = tid;
            float v;
            if (j < 160) v = g1b[j];
            else if (j < 200) v = pgb[1] * xcat[164 + 82 + (j - 160)];
            else v = xcat[164 + 124 + (j - 200)];
            skin[j] = v;
        }
        __syncthreads();
        gru_glu<128, 240, 64, 64>(st, skin, s2, g2b, gi, gh, red);     // G2IH,G2HH,GLU2

        if (tid < 208) {
            int j = tid;
            float v;
            if (j < 128) v = g2b[j];
            else if (j < 168) v = pgb[2] * xcat[164 + 82 + (j - 128)];
            else v = xcat[164 + 124 + (j - 168)];
            skin[j] = v;
        }
        __syncthreads();
        gru_glu<128, 208, 64, 64>(st, skin, s3, g3b, gi, gh, red);     // G3IH,G3HH,GLU3

        for (int i = tid; i < 688; i += NT) {
            int j = i;
            float v;
            if (j < 160) v = g1b[j];
            else if (j < 288) v = g2b[j - 160];
            else if (j < 416) v = g3b[j - 288];
            else if (j < 608) v = fwc_out[j - 416];
            else if (j < 648) v = pgb[3] * xcat[164 + 82 + (j - 608)];
            else v = xcat[164 + 124 + (j - 648)];
            skin[j] = v;
        }
        __syncthreads();
        matvec_s<688, 128, 192, 1>(st, skin, buf_t, red);              // SKIP
        matvec_s<128, 128, 128, 0>(st, buf_t, gh, red);                // SKIPG
        if (tid < 128) skipv[tid] = buf_t[tid] * sigf(gh[tid]);
        __syncthreads();

        matvec_s<128, 40, 128, 1>(st, skipv, gi, red);                 // SIG
        if (tid < 40) {
            float v = gi[tid] * sgain[0];
            exc[(base + tid) & 255] = v;
            out[(size_t)b0 * 80000 + s * 40 + tid] = v;
        }
        __syncthreads();
        base = (base + 40) & 255;
    }
    CLUSTER_SYNC();
}

// ---------------- launch ----------------
extern "C" void kernel_launch(void* const* d_in, const int* in_sizes, int n_in,
                              void* d_out, int out_size) {
    const float* features = (const float*)d_in[0];
    const int*   period   = (const int*)d_in[1];
    const float* pembed   = (const float*)d_in[2];
    const float* fd1_w    = (const float*)d_in[3];
    const float* fconv1_w = (const float*)d_in[4];
    const float* fd2_w    = (const float*)d_in[5];
    const float* cg_w     = (const float*)d_in[6];
    const float* cg_b     = (const float*)d_in[7];
    const float* gout_b   = (const float*)d_in[23];
    float* out = (float*)d_out;

    WP wp;
    for (int i = 0; i < 15; i++) wp.p[i] = (const float*)d_in[8 + i];

    cudaFuncSetAttribute(k_convn, cudaFuncAttributeMaxDynamicSharedMemorySize, CONV_SMEM);
    cudaFuncSetAttribute(k_fd2n, cudaFuncAttributeMaxDynamicSharedMemorySize, FD2_SMEM);
    cudaFuncSetAttribute(k_scan, cudaFuncAttributeMaxDynamicSharedMemorySize, SCAN_DSMEM);

    dim3 tg((130560 + 255) / 256, 15);
    k_transpose_all<<<tg, 256>>>(wp);
    k_fd1n<<<BATCH, 256>>>(features, period, pembed, fd1_w);
    k_convn<<<dim3(BATCH, 2), 128, CONV_SMEM>>>(fconv1_w);
    k_fd2n<<<BATCH, 320, FD2_SMEM>>>(fd2_w, cg_w, cg_b);
    k_scan<<<BATCH, NT, SCAN_DSMEM>>>(period, gout_b, out);   // 64 clusters of 2
    (void)in_sizes; (void)n_in; (void)out_size;
}